// round 13
// baseline (speedup 1.0000x reference)
#include <cuda_runtime.h>
#include <cstdint>

// DeepInsightEncoding: out[b,h,w,c], c in {stamp, scatter, rowcopy, nd, bars}
// B=512, D=32, H=W=128. Output fp32 [512,128,128,5] = 168 MB -> HBM-write bound.
//
// R13: amortize overheads. 8 warps x 2 rows/warp per CTA (prologue reused),
// all 16 staged rows contiguous -> ONE 40KB cp.async.bulk per CTA
// (one fence/commit/wait per CTA instead of per row).

#define THREADS 256            // 8 warps, 2 rows each
#define NWARPS 8
#define ROWS_PER_CTA 16
#define ROW_F4 160             // 128 px * 5 ch / 4 = 2560 B per row

__global__ void __launch_bounds__(THREADS)
deepinsight_kernel(const float* __restrict__ inputs,   // [512,32]
                   const float* __restrict__ stamp,    // [128,128]
                   const int*   __restrict__ coords,   // [32,2]
                   float*       __restrict__ out)      // [512,128,128,5]
{
    __shared__ __align__(16) float4 stage[ROWS_PER_CTA][ROW_F4]; // 40 KB contiguous

    const int b    = blockIdx.x >> 3;
    const int h0   = (blockIdx.x & 7) * ROWS_PER_CTA;
    const int warp = threadIdx.x >> 5;
    const int lane = threadIdx.x & 31;

    // ---- per-warp register prologue (done once, reused for 2 rows) ----
    const float v  = __ldg(inputs + b * 32 + lane);       // x[lane]
    const int2  cd = __ldg((const int2*)coords + lane);   // (row, col) for d=lane

    int bh = (int)rintf(v * 128.0f);                      // round-half-even == jnp.round
    bh = min(max(bh, 0), 128);

    float mn = v, mx = v;
    #pragma unroll
    for (int o = 16; o; o >>= 1) {
        mn = fminf(mn, __shfl_xor_sync(0xffffffffu, mn, o));
        mx = fmaxf(mx, __shfl_xor_sync(0xffffffffu, mx, o));
    }
    const float inv_range = 1.0f / (mx - mn);

    // bar columns: first at 17, stride 3, 32 bars (bar_w=1, gap=2, beg=15)
    int bi[4];
    #pragma unroll
    for (int k = 0; k < 4; k++) {
        int w = lane * 4 + k - 17;
        bi[k] = (w >= 0 && w <= 93 && (w % 3) == 0) ? (w / 3) : -1;
    }
    // bar height for this lane's columns (row-independent; compare h later)
    int bhk[4];
    #pragma unroll
    for (int k = 0; k < 4; k++)
        bhk[k] = __shfl_sync(0xffffffffu, bh, bi[k] < 0 ? 0 : bi[k]);

    const float ndbase = v;   // nd col operand for cols 4*lane..+3

    // ---- 2 rows per warp ----
    #pragma unroll
    for (int rr = 0; rr < 2; rr++) {
        const int hl = warp * 2 + rr;
        const int h  = h0 + hl;

        const float rc  = __shfl_sync(0xffffffffu, v, h >> 2);   // rowcopy
        const float ndv = fabsf(rc - ndbase) * inv_range;

        float bar[4];
        #pragma unroll
        for (int k = 0; k < 4; k++)
            bar[k] = (bi[k] >= 0 && h < bhk[k]) ? 1.0f : 0.0f;

        const float4 s4 = __ldg((const float4*)(stamp + h * 128 + lane * 4));

        // 20 floats -> staging (STS.128 @ 80B stride: conflict-free)
        float4* const stg = stage[hl];
        stg[lane * 5 + 0] = make_float4(s4.x,   0.0f,   rc,     ndv);
        stg[lane * 5 + 1] = make_float4(bar[0], s4.y,   0.0f,   rc);
        stg[lane * 5 + 2] = make_float4(ndv,    bar[1], s4.z,   0.0f);
        stg[lane * 5 + 3] = make_float4(rc,     ndv,    bar[2], s4.w);
        stg[lane * 5 + 4] = make_float4(0.0f,   rc,     ndv,    bar[3]);
        __syncwarp();

        // scatter patch: duplicates sum via atomicAdd (tf.scatter_nd)
        if (cd.x == h)
            atomicAdd(&((float*)stg)[cd.y * 5 + 1], v);
    }

    __syncthreads();

    // ---- drain: ONE 40KB bulk store for the whole 16-row block ----
    if (threadIdx.x == 0) {
        uint32_t saddr;
        asm volatile("{ .reg .u64 t; cvta.to.shared.u64 t, %1; cvt.u32.u64 %0, t; }"
                     : "=r"(saddr) : "l"(&stage[0][0]));
        float* gptr = out + (size_t)(b * 128 + h0) * 640;   // 128*5 floats/row
        asm volatile("fence.proxy.async.shared::cta;" ::: "memory");
        asm volatile("cp.async.bulk.global.shared::cta.bulk_group [%0], [%1], %2;"
                     :: "l"(gptr), "r"(saddr), "r"((unsigned)(ROWS_PER_CTA * 2560)) : "memory");
        asm volatile("cp.async.bulk.commit_group;" ::: "memory");
        asm volatile("cp.async.bulk.wait_group.read 0;" ::: "memory");
    }
}

extern "C" void kernel_launch(void* const* d_in, const int* in_sizes, int n_in,
                              void* d_out, int out_size)
{
    const float* inputs = (const float*)d_in[0];   // [512,32]
    const float* stamp  = (const float*)d_in[1];   // [128,128,1]
    const int*   coords = (const int*)d_in[2];     // [32,2]
    float*       out    = (float*)d_out;           // [512,128,128,5]

    deepinsight_kernel<<<512 * 8, THREADS>>>(inputs, stamp, coords, out);
}